// round 2
// baseline (speedup 1.0000x reference)
#include <cuda_runtime.h>
#include <cstddef>

// CorrVolume 1/4: out[b,d,h,w] = sum_c L[b,h,w,c] * R[b,h,w-d,c]  (0 for w<d)
// B=8, H=160, W=320, C=128, D=48, fp32.
//
// Banded-GEMM register tiling:
//   block = one (b,h) row x 160-wide w-tile (2 tiles cover W=320 exactly)
//   120 active threads = 6 d-groups (td=8) x 20 w-groups (tw=8 as two quads
//   at 4j and 4j+80 -> conflict-free lane-consecutive LDS.128 on the FMA side)
//   smem holds transposed [c][w] stage tiles (CS=32 channels per stage).

namespace {
constexpr int B = 8, H = 160, W = 320, C = 128, D = 48;
constexpr int WT = 160;   // w-tile width
constexpr int RW = 208;   // R tile rows: WT + 48 halo
constexpr int CS = 32;    // channels per smem stage
constexpr int PL = 164;   // sL pitch in words (160 + 4 pad, mult of 4)
constexpr int PR = 212;   // sR pitch in words (208 + 4 pad, mult of 4)
constexpr int NT = 128;   // threads per block
}

__global__ __launch_bounds__(NT, 3)
void corr_volume_kernel(const float* __restrict__ Lg,
                        const float* __restrict__ Rg,
                        float* __restrict__ Og)
{
    __shared__ __align__(16) float sL[CS * PL];
    __shared__ __align__(16) float sR[CS * PR];

    const int w0 = blockIdx.x * WT;   // 0 or 160
    const int h  = blockIdx.y;
    const int b  = blockIdx.z;

    const int tid  = threadIdx.x;
    const int lane = tid & 31;
    const int wp   = tid >> 5;        // warp id, 0..3

    const bool active = tid < 120;
    const int i = tid / 20;           // d-group: d = 8*i + dd
    const int j = tid % 20;           // w-group: w = w0 + 4*j (+80)

    const float* Lrow = Lg + ((size_t)(b * H + h) * W) * C;
    const float* Rrow = Rg + ((size_t)(b * H + h) * W) * C;

    float acc[8][8];
#pragma unroll
    for (int dd = 0; dd < 8; dd++)
#pragma unroll
        for (int u = 0; u < 8; u++) acc[dd][u] = 0.0f;

    // sR index of element w' is (w' - w0) + 48; quad0 aligned window base:
    // w' = 4j - 8i - 8  ->  idx = 4j - 8i + 40  (in [0, 116], mult of 4)
    const int rb0 = active ? (4 * j - 8 * i + 40) : 0;
    const int aL0 = active ? (4 * j) : 0;

    for (int cs = 0; cs < C; cs += CS) {
        // ---- stage load: transpose [w][c] -> [c][w]; coalesced 128B per row ----
#pragma unroll
        for (int r = wp; r < WT; r += NT / 32) {
            sL[lane * PL + r] = __ldg(&Lrow[(size_t)(w0 + r) * C + cs + lane]);
        }
#pragma unroll
        for (int r = wp; r < RW; r += NT / 32) {
            const int w = w0 + r - 48;
            sR[lane * PR + r] = (w >= 0) ? __ldg(&Rrow[(size_t)w * C + cs + lane]) : 0.0f;
        }
        __syncthreads();

        if (active) {
#pragma unroll 2
            for (int c = 0; c < CS; c++) {
                const float* lc = sL + c * PL;
                const float* rc = sR + c * PR;

                const float4 a0 = *(const float4*)(lc + aL0);        // w quad0
                const float4 a1 = *(const float4*)(lc + aL0 + 80);   // w quad1
                const float4 q0 = *(const float4*)(rc + rb0);
                const float4 q1 = *(const float4*)(rc + rb0 + 4);
                const float4 q2 = *(const float4*)(rc + rb0 + 8);
                const float4 q3 = *(const float4*)(rc + rb0 + 80);
                const float4 q4 = *(const float4*)(rc + rb0 + 84);
                const float4 q5 = *(const float4*)(rc + rb0 + 88);

                const float a[8]  = {a0.x, a0.y, a0.z, a0.w, a1.x, a1.y, a1.z, a1.w};
                const float r0[12] = {q0.x, q0.y, q0.z, q0.w,
                                      q1.x, q1.y, q1.z, q1.w,
                                      q2.x, q2.y, q2.z, q2.w};
                const float r1[12] = {q3.x, q3.y, q3.z, q3.w,
                                      q4.x, q4.y, q4.z, q4.w,
                                      q5.x, q5.y, q5.z, q5.w};

                // acc[dd][u]   : w = w0 + 4j + u,        d = 8i + dd
                //   R word idx = (4j + u) - (8i + dd) - (4j - 8i - 8) = 8 + u - dd
#pragma unroll
                for (int dd = 0; dd < 8; dd++) {
#pragma unroll
                    for (int u = 0; u < 4; u++) {
                        acc[dd][u]     = fmaf(a[u],     r0[8 + u - dd], acc[dd][u]);
                        acc[dd][u + 4] = fmaf(a[u + 4], r1[8 + u - dd], acc[dd][u + 4]);
                    }
                }
            }
        }
        __syncthreads();
    }

    if (active) {
#pragma unroll
        for (int dd = 0; dd < 8; dd++) {
            const int d = 8 * i + dd;
            float* orow = Og + (((size_t)(b * D + d) * H + h) * W);
            *(float4*)(orow + w0 + 4 * j) =
                make_float4(acc[dd][0], acc[dd][1], acc[dd][2], acc[dd][3]);
            *(float4*)(orow + w0 + 80 + 4 * j) =
                make_float4(acc[dd][4], acc[dd][5], acc[dd][6], acc[dd][7]);
        }
    }
}

extern "C" void kernel_launch(void* const* d_in, const int* in_sizes, int n_in,
                              void* d_out, int out_size)
{
    (void)in_sizes; (void)n_in; (void)out_size;
    const float* L = (const float*)d_in[0];
    const float* R = (const float*)d_in[1];
    float* O = (float*)d_out;

    dim3 grid(W / WT, H, B);   // (2, 160, 8)
    corr_volume_kernel<<<grid, NT>>>(L, R, O);
}

// round 4
// speedup vs baseline: 1.3742x; 1.3742x over previous
#include <cuda_runtime.h>
#include <cstddef>

// CorrVolume 1/4: out[b,d,h,w] = sum_c L[b,h,w,c] * R[b,h,w-d,c]  (0 for w<d)
// B=8, H=160, W=320, C=128, D=48, fp32.
//
// R3: 16d x 4w thread tile (0.375 smem words / FMA) + conflict-free
//     transposing loader (coalesced scalar LDG x4 -> one STS.128).
//   block = one (b,h) row x 160-wide w-tile (2 tiles cover W=320 exactly)
//   120 active threads = 3 d-groups (td=16) x 40 w-groups (tw=4)
//   smem holds transposed [c][w] stage tiles (CS=32 channels per stage).

namespace {
constexpr int B = 8, H = 160, W = 320, C = 128, D = 48;
constexpr int WT = 160;   // w-tile width
constexpr int RW = 208;   // R tile rows: WT + 48 halo
constexpr int CS = 32;    // channels per smem stage
constexpr int PL = 164;   // sL pitch in words (160 + 4 pad, mult of 4)
constexpr int PR = 212;   // sR pitch in words (208 + 4 pad, mult of 4)
constexpr int NT = 128;   // threads per block
}

__global__ __launch_bounds__(NT, 3)
void corr_volume_kernel(const float* __restrict__ Lg,
                        const float* __restrict__ Rg,
                        float* __restrict__ Og)
{
    __shared__ __align__(16) float sL[CS * PL];
    __shared__ __align__(16) float sR[CS * PR];

    const int w0 = blockIdx.x * WT;   // 0 or 160
    const int h  = blockIdx.y;
    const int b  = blockIdx.z;

    const int tid  = threadIdx.x;
    const int lane = tid & 31;        // loader: channel within stage
    const int wp   = tid >> 5;        // warp id, 0..3

    const bool active = tid < 120;
    const int i = tid / 40;           // d-group: d = 16*i + dd
    const int j = tid % 40;           // w-group: w = w0 + 4*j + u

    const float* Lrow = Lg + ((size_t)(b * H + h) * W) * C;
    const float* Rrow = Rg + ((size_t)(b * H + h) * W) * C;

    float acc[16][4];
#pragma unroll
    for (int dd = 0; dd < 16; dd++)
#pragma unroll
        for (int u = 0; u < 4; u++) acc[dd][u] = 0.0f;

    // sR word index of column w' is (w' - w0) + 48.
    // Thread window: w' = 4j + u - 16i - dd, u in [0,3], dd in [0,15]
    //   -> idx in [4j-16i+33, 4j-16i+51]; quad-aligned base:
    const int rb0 = active ? (4 * j - 16 * i + 32) : 0;   // in [0, 188]
    const int aL0 = active ? (4 * j) : 0;

    for (int cs = 0; cs < C; cs += CS) {
        // ---- stage load: transpose [w][c] -> [c][w] ----
        // lane = channel; each task: 4 coalesced scalar LDGs (rows r4..r4+3,
        // channel cs+lane) -> one STS.128 at s[lane*pitch + r4].
        // Store banks per 8-lane phase: lane*4 + {0..3} mod 32 = all 32 banks.
#pragma unroll
        for (int ch = wp; ch < WT / 4; ch += NT / 32) {
            const int r4 = ch * 4;
            float v0 = __ldg(&Lrow[(size_t)(w0 + r4 + 0) * C + cs + lane]);
            float v1 = __ldg(&Lrow[(size_t)(w0 + r4 + 1) * C + cs + lane]);
            float v2 = __ldg(&Lrow[(size_t)(w0 + r4 + 2) * C + cs + lane]);
            float v3 = __ldg(&Lrow[(size_t)(w0 + r4 + 3) * C + cs + lane]);
            *(float4*)&sL[lane * PL + r4] = make_float4(v0, v1, v2, v3);
        }
#pragma unroll
        for (int ch = wp; ch < RW / 4; ch += NT / 32) {
            const int r4 = ch * 4;
            float v[4];
#pragma unroll
            for (int k = 0; k < 4; k++) {
                const int w = w0 + r4 + k - 48;
                v[k] = (w >= 0) ? __ldg(&Rrow[(size_t)w * C + cs + lane]) : 0.0f;
            }
            *(float4*)&sR[lane * PR + r4] = make_float4(v[0], v[1], v[2], v[3]);
        }
        __syncthreads();

        if (active) {
#pragma unroll 2
            for (int c = 0; c < CS; c++) {
                const float* lc = sL + c * PL;
                const float* rc = sR + c * PR;

                const float4 av = *(const float4*)(lc + aL0);
                const float4 q0 = *(const float4*)(rc + rb0);
                const float4 q1 = *(const float4*)(rc + rb0 + 4);
                const float4 q2 = *(const float4*)(rc + rb0 + 8);
                const float4 q3 = *(const float4*)(rc + rb0 + 12);
                const float4 q4 = *(const float4*)(rc + rb0 + 16);

                const float a[4]  = {av.x, av.y, av.z, av.w};
                const float r[20] = {q0.x, q0.y, q0.z, q0.w,
                                     q1.x, q1.y, q1.z, q1.w,
                                     q2.x, q2.y, q2.z, q2.w,
                                     q3.x, q3.y, q3.z, q3.w,
                                     q4.x, q4.y, q4.z, q4.w};

                // acc[dd][u]: w = w0+4j+u, d = 16i+dd
                //   sR word = 4j+u-16i-dd+48 -> offset = u - dd + 16  (in [1,19])
#pragma unroll
                for (int dd = 0; dd < 16; dd++) {
#pragma unroll
                    for (int u = 0; u < 4; u++) {
                        acc[dd][u] = fmaf(a[u], r[u - dd + 16], acc[dd][u]);
                    }
                }
            }
        }
        __syncthreads();
    }

    if (active) {
#pragma unroll
        for (int dd = 0; dd < 16; dd++) {
            const int d = 16 * i + dd;
            float* orow = Og + (((size_t)(b * D + d) * H + h) * W);
            *(float4*)(orow + w0 + 4 * j) =
                make_float4(acc[dd][0], acc[dd][1], acc[dd][2], acc[dd][3]);
        }
    }
}

extern "C" void kernel_launch(void* const* d_in, const int* in_sizes, int n_in,
                              void* d_out, int out_size)
{
    (void)in_sizes; (void)n_in; (void)out_size;
    const float* L = (const float*)d_in[0];
    const float* R = (const float*)d_in[1];
    float* O = (float*)d_out;

    dim3 grid(W / WT, H, B);   // (2, 160, 8)
    corr_volume_kernel<<<grid, NT>>>(L, R, O);
}